// round 6
// baseline (speedup 1.0000x reference)
#include <cuda_runtime.h>
#include <cstdint>

#define N_NODES 50000
#define DEG     32
#define HEADS   4
#define OUT_F   16
#define IN_F    64
#define EDIM    (HEADS * OUT_F)   // 64 combined (h,o) features
#define PB_NODES 32               // nodes per proj tile

typedef unsigned long long ull;

// Scratch: projected queries/keys. Node-major rows of 64 floats (256B), with
// a PERMUTED feature order so gat's 8-lane layout is wavefront-optimal:
//   slot s (s<32):  feature = 8*(s>>2) + (s&3)
//   slot s (s>=32): feature = 8*((s-32)>>2) + 4 + (s&3)
// i.e. lane wl (0..7) owns features [8wl, 8wl+8) via float4s at slots
// 4wl (line 0) and 32+4wl (line 1).
__device__ __align__(16) float g_Qf[N_NODES * EDIM];
__device__ __align__(16) float g_Kf[N_NODES * EDIM];

// ---------------------------------------------------------------------------
// f32x2 packed helpers (sm_103a)
// ---------------------------------------------------------------------------
__device__ __forceinline__ ull pack2(float a, float b) {
    ull r; asm("mov.b64 %0, {%1, %2};" : "=l"(r) : "f"(a), "f"(b)); return r;
}
__device__ __forceinline__ float2 unpack2(ull v) {
    float2 r; asm("mov.b64 {%0, %1}, %2;" : "=f"(r.x), "=f"(r.y) : "l"(v)); return r;
}
__device__ __forceinline__ void fma2(ull& d, ull a, ull b) {
    asm("fma.rn.f32x2 %0, %1, %2, %0;" : "+l"(d) : "l"(a), "l"(b));
}
__device__ __forceinline__ float ex2f(float x) {
    float r; asm("ex2.approx.ftz.f32 %0, %1;" : "=f"(r) : "f"(x)); return r;
}

// slot(e): inverse of the permutation above
__device__ __forceinline__ int slot_of(int e) {
    int wl = e >> 3, q = e & 7;
    return (q < 4) ? (4 * wl + q) : (32 + 4 * wl + (q - 4));
}

// ---------------------------------------------------------------------------
// Kernel 1: projection.  dst[n][slot(e)] = sum_i w[e][i] * Q[i][n]
// Block = 128 threads = 32 nodes x 2 e-halves x 2 i-halves.
// i-split keeps qq at 16 ull (32 regs) -> ~48 regs -> 62% occupancy; the two
// i-half partials are summed in the SMEM store pass. Weights read directly
// via uniform LDG.128 (L1-resident, 1 wavefront). Dual fma2 chains per output.
// ---------------------------------------------------------------------------
__global__ __launch_bounds__(128) void proj_kernel(
    const float* __restrict__ Q,      // [IN_F][N_NODES]
    const float* __restrict__ qw,     // [EDIM][IN_F]
    const float* __restrict__ kw)     // [EDIM][IN_F]
{
    __shared__ float sS[2][PB_NODES][EDIM + 1];   // 16.6 KB, pad-65 pitch

    const float* w   = blockIdx.y ? kw : qw;
    float*       dst = blockIdx.y ? g_Kf : g_Qf;

    const int n0  = blockIdx.x * PB_NODES;
    const int nl  = threadIdx.x & 31;
    const int eh  = ((threadIdx.x >> 5) & 1) * 32;   // my 32-feature half
    const int ih  = threadIdx.x >> 6;                // my input half (0/1)
    const int ip0 = ih * 16;                         // first input PAIR
    const int n   = n0 + nl;
    const int nld = (n < N_NODES) ? n : (N_NODES - 1);

    // My half of the input column, packed in pairs (16 ull = 32 regs).
    ull qq[16];
#pragma unroll
    for (int k = 0; k < 16; k++) {
        int i2 = ip0 + k;
        float a = Q[(2 * i2 + 0) * N_NODES + nld];
        float b = Q[(2 * i2 + 1) * N_NODES + nld];
        qq[k] = pack2(a, b);
    }

#pragma unroll 2
    for (int ee = 0; ee < 32; ee++) {
        int e = eh + ee;
        const ulonglong2* wr =
            reinterpret_cast<const ulonglong2*>(w + e * IN_F + 2 * ip0);
        ull a0 = 0ull, a1 = 0ull;            // dual chains (8 deep each)
#pragma unroll
        for (int k4 = 0; k4 < 8; k4++) {
            ulonglong2 wp = __ldg(&wr[k4]);  // uniform across warp: 1 wf
            fma2(a0, wp.x, qq[2 * k4 + 0]);
            fma2(a1, wp.y, qq[2 * k4 + 1]);
        }
        float2 r0 = unpack2(a0), r1 = unpack2(a1);
        sS[ih][nl][slot_of(e)] = (r0.x + r0.y) + (r1.x + r1.y);
    }
    __syncthreads();

    // Sum the two i-half partials; coalesced store of the [nodes][64] tile.
    const int nmax = min(PB_NODES, N_NODES - n0);
    for (int idx = threadIdx.x; idx < nmax * EDIM; idx += 128) {
        int r = idx >> 6, sl = idx & 63;
        dst[(n0 + r) * EDIM + sl] = sS[0][r][sl] + sS[1][r][sl];
    }
}

// ---------------------------------------------------------------------------
// Kernel 2: gather + attention + aggregate. Max-free softmax (exp2 domain),
// 4 neighbors/iter. Warp per node; group g = lane>>3 handles neighbor 4t+g;
// lane wl = lane&7 owns features [8wl, 8wl+8) (head wl>>1) via two float4
// loads, one per cache line of the permuted row -> 2 lines/neighbor-row
// (wavefront-optimal). Head reduction = single xor-1 shuffle (2 lanes/head).
// Final merge of the 4 groups' (s, acc) via xor-8 / xor-16.
// ---------------------------------------------------------------------------
__global__ __launch_bounds__(256) void gat_kernel(
    const int*   __restrict__ adj,    // [N_NODES][DEG]
    const float* __restrict__ aw,     // [EDIM]
    float*       __restrict__ out)    // [EDIM][N_NODES]
{
    const unsigned FULL = 0xffffffffu;
    const float LOG2E = 1.4426950408889634f;
    const int warp = threadIdx.x >> 5;
    const int lane = threadIdx.x & 31;
    const int g    = lane >> 3;
    const int wl   = lane & 7;
    const int n = blockIdx.x * 8 + warp;          // grid exact: 6250*8 = 50000

    __shared__ float sOut[EDIM][9];               // pitch 9 to spread banks

    int    j  = adj[n * DEG + lane];
    // permuted q row: slots 4wl (line 0) and 32+4wl (line 1)
    float4 qA = *reinterpret_cast<const float4*>(&g_Qf[n * EDIM + 4 * wl]);
    float4 qB = *reinterpret_cast<const float4*>(&g_Qf[n * EDIM + 32 + 4 * wl]);
    // aw in TRUE feature order: my features are contiguous [8wl, 8wl+8)
    float4 wA = *reinterpret_cast<const float4*>(&aw[8 * wl]);
    float4 wB = *reinterpret_cast<const float4*>(&aw[8 * wl + 4]);
    wA.x *= LOG2E; wA.y *= LOG2E; wA.z *= LOG2E; wA.w *= LOG2E;
    wB.x *= LOG2E; wB.y *= LOG2E; wB.z *= LOG2E; wB.w *= LOG2E;

    float  s = 0.f;
    float4 aA = make_float4(0.f, 0.f, 0.f, 0.f);
    float4 aB = make_float4(0.f, 0.f, 0.f, 0.f);

#pragma unroll
    for (int t = 0; t < DEG / 4; t++) {
        int jk = __shfl_sync(FULL, j, (t << 2) | g);
        float4 kA = make_float4(0.f, 0.f, 0.f, 0.f);
        float4 kB = make_float4(0.f, 0.f, 0.f, 0.f);
        if (jk >= 0) {   // uniform within 8-lane group
            kA = *reinterpret_cast<const float4*>(&g_Kf[jk * EDIM + 4 * wl]);
            kB = *reinterpret_cast<const float4*>(&g_Kf[jk * EDIM + 32 + 4 * wl]);
        }

        // leaky_relu(x) = max(x, 0.01x), dot with (log2e-scaled) aw
        float l, p;
        l = qA.x + kA.x; l = fmaxf(l, 0.01f * l); p = wA.x * l;
        l = qA.y + kA.y; l = fmaxf(l, 0.01f * l); p = fmaf(wA.y, l, p);
        l = qA.z + kA.z; l = fmaxf(l, 0.01f * l); p = fmaf(wA.z, l, p);
        l = qA.w + kA.w; l = fmaxf(l, 0.01f * l); p = fmaf(wA.w, l, p);
        l = qB.x + kB.x; l = fmaxf(l, 0.01f * l); p = fmaf(wB.x, l, p);
        l = qB.y + kB.y; l = fmaxf(l, 0.01f * l); p = fmaf(wB.y, l, p);
        l = qB.z + kB.z; l = fmaxf(l, 0.01f * l); p = fmaf(wB.z, l, p);
        l = qB.w + kB.w; l = fmaxf(l, 0.01f * l); p = fmaf(wB.w, l, p);

        // 16 feats of my head live on lanes (wl^1 pair): one xor-1 shuffle
        p += __shfl_xor_sync(FULL, p, 1);

        // max-free softmax term; padded edge -> weight 0
        float e = (jk >= 0) ? ex2f(p) : 0.f;
        s += e;
        aA.x = fmaf(e, kA.x, aA.x);
        aA.y = fmaf(e, kA.y, aA.y);
        aA.z = fmaf(e, kA.z, aA.z);
        aA.w = fmaf(e, kA.w, aA.w);
        aB.x = fmaf(e, kB.x, aB.x);
        aB.y = fmaf(e, kB.y, aB.y);
        aB.z = fmaf(e, kB.z, aB.z);
        aB.w = fmaf(e, kB.w, aB.w);
    }

    // merge the 4 neighbor-groups (same wl across g): xor 8, then xor 16
#pragma unroll
    for (int d = 8; d <= 16; d <<= 1) {
        s    += __shfl_xor_sync(FULL, s, d);
        aA.x += __shfl_xor_sync(FULL, aA.x, d);
        aA.y += __shfl_xor_sync(FULL, aA.y, d);
        aA.z += __shfl_xor_sync(FULL, aA.z, d);
        aA.w += __shfl_xor_sync(FULL, aA.w, d);
        aB.x += __shfl_xor_sync(FULL, aB.x, d);
        aB.y += __shfl_xor_sync(FULL, aB.y, d);
        aB.z += __shfl_xor_sync(FULL, aB.z, d);
        aB.w += __shfl_xor_sync(FULL, aB.w, d);
    }

    // all-pad rows: s == 0, acc == 0 -> output exactly 0 (matches reference)
    float inv = __frcp_rn(fmaxf(s, 1e-30f));
    if (g == 0) {   // un-permute: my true features are [8wl, 8wl+8)
        sOut[8 * wl + 0][warp] = aA.x * inv;
        sOut[8 * wl + 1][warp] = aA.y * inv;
        sOut[8 * wl + 2][warp] = aA.z * inv;
        sOut[8 * wl + 3][warp] = aA.w * inv;
        sOut[8 * wl + 4][warp] = aB.x * inv;
        sOut[8 * wl + 5][warp] = aB.y * inv;
        sOut[8 * wl + 6][warp] = aB.z * inv;
        sOut[8 * wl + 7][warp] = aB.w * inv;
    }
    __syncthreads();

    // Coalesced store: 512 elements, 8 consecutive n per feature row.
    const int n0 = blockIdx.x * 8;
#pragma unroll
    for (int idx = threadIdx.x; idx < EDIM * 8; idx += 256) {
        int e  = idx >> 3;
        int nn = idx & 7;
        out[e * N_NODES + n0 + nn] = sOut[e][nn];
    }
}

// ---------------------------------------------------------------------------
extern "C" void kernel_launch(void* const* d_in, const int* in_sizes, int n_in,
                              void* d_out, int out_size)
{
    const int*   adj = (const int*)  d_in[0];   // [50000*32] int32
    const float* Q   = (const float*)d_in[1];   // [64*50000]
    const float* qw  = (const float*)d_in[2];   // [4*16*64]
    const float* kw  = (const float*)d_in[3];   // [4*16*64]
    const float* aw  = (const float*)d_in[4];   // [4*16]
    float* out = (float*)d_out;                 // [4*16*50000]

    (void)in_sizes; (void)n_in; (void)out_size;

    dim3 pgrid((N_NODES + PB_NODES - 1) / PB_NODES, 2);   // 1563 x 2
    proj_kernel<<<pgrid, 128>>>(Q, qw, kw);
    gat_kernel<<<N_NODES / 8, 256>>>(adj, aw, out);
}

// round 7
// speedup vs baseline: 1.3926x; 1.3926x over previous
#include <cuda_runtime.h>
#include <cstdint>

#define N_NODES 50000
#define DEG     32
#define HEADS   4
#define OUT_F   16
#define IN_F    64
#define EDIM    (HEADS * OUT_F)   // 64 combined (h,o) features
#define PB_NODES 64               // nodes per proj block

typedef unsigned long long ull;

// Scratch: projected queries/keys, node-major (256B contiguous per node),
// natural feature order.
__device__ __align__(16) float g_Qf[N_NODES * EDIM];
__device__ __align__(16) float g_Kf[N_NODES * EDIM];

// ---------------------------------------------------------------------------
// f32x2 packed helpers (sm_103a)
// ---------------------------------------------------------------------------
__device__ __forceinline__ ull pack2(float a, float b) {
    ull r; asm("mov.b64 %0, {%1, %2};" : "=l"(r) : "f"(a), "f"(b)); return r;
}
__device__ __forceinline__ float2 unpack2(ull v) {
    float2 r; asm("mov.b64 {%0, %1}, %2;" : "=f"(r.x), "=f"(r.y) : "l"(v)); return r;
}
__device__ __forceinline__ void fma2(ull& d, ull a, ull b) {
    asm("fma.rn.f32x2 %0, %1, %2, %0;" : "+l"(d) : "l"(a), "l"(b));
}
__device__ __forceinline__ ull add2(ull a, ull b) {
    ull r; asm("add.rn.f32x2 %0, %1, %2;" : "=l"(r) : "l"(a), "l"(b)); return r;
}
__device__ __forceinline__ float ex2f(float x) {
    float r; asm("ex2.approx.ftz.f32 %0, %1;" : "=f"(r) : "f"(x)); return r;
}

// ---------------------------------------------------------------------------
// Kernel 1: projection.  dst[n][e] = sum_i w[e][i] * Q[i][n]
// Block 256 = 8 warps = 4 node-groups(16 nodes) x 2 e-halves.
// Within a warp, lanes 0-15 / 16-31 take the two i-halves of the same 16
// nodes: qq shrinks to 16 ull (32 regs) and the i-partials merge with one
// shfl_xor(16) per output. Weights smem-resident; SMEM-staged coalesced store.
// ---------------------------------------------------------------------------
__global__ __launch_bounds__(256) void proj_kernel(
    const float* __restrict__ Q,      // [IN_F][N_NODES]
    const float* __restrict__ qw,     // [EDIM][IN_F]
    const float* __restrict__ kw)     // [EDIM][IN_F]
{
    const unsigned FULL = 0xffffffffu;
    __shared__ ull   sW[EDIM][IN_F / 2];        // 16 KB (this matrix)
    __shared__ float sS[PB_NODES][EDIM + 1];    // 16.6 KB, pad-65

    const float* w   = blockIdx.y ? kw : qw;
    float*       dst = blockIdx.y ? g_Kf : g_Qf;

    const ull* w2 = reinterpret_cast<const ull*>(w);
#pragma unroll
    for (int t = threadIdx.x; t < EDIM * (IN_F / 2); t += 256)
        sW[t >> 5][t & 31] = w2[t];
    __syncthreads();

    const int warp = threadIdx.x >> 5;
    const int lane = threadIdx.x & 31;
    const int ih   = lane >> 4;                 // i-half (0/1)
    const int eh   = (warp & 1) * 32;           // e-half
    const int nl   = (warp >> 1) * 16 + (lane & 15);   // node-local 0..63
    const int n0   = blockIdx.x * PB_NODES;
    const int n    = n0 + nl;
    const int nld  = (n < N_NODES) ? n : (N_NODES - 1);

    // My i-half of the input column, packed in pairs (16 ull = 32 regs).
    ull qq[16];
#pragma unroll
    for (int k = 0; k < 16; k++) {
        int i2 = ih * 16 + k;
        float a = Q[(2 * i2 + 0) * N_NODES + nld];
        float b = Q[(2 * i2 + 1) * N_NODES + nld];
        qq[k] = pack2(a, b);
    }

#pragma unroll 1
    for (int ee = 0; ee < 32; ee += 2) {
        int e0 = eh + ee;
        const ulonglong2* w0 =
            reinterpret_cast<const ulonglong2*>(&sW[e0][ih * 16]);
        const ulonglong2* w1 =
            reinterpret_cast<const ulonglong2*>(&sW[e0 + 1][ih * 16]);
        ull a0 = 0ull, a1 = 0ull;               // two independent chains
#pragma unroll
        for (int k4 = 0; k4 < 8; k4++) {
            ulonglong2 p0 = w0[k4];             // LDS.128 (2 bcast groups)
            ulonglong2 p1 = w1[k4];
            fma2(a0, p0.x, qq[2 * k4 + 0]); fma2(a0, p0.y, qq[2 * k4 + 1]);
            fma2(a1, p1.x, qq[2 * k4 + 0]); fma2(a1, p1.y, qq[2 * k4 + 1]);
        }
        float2 u0 = unpack2(a0), u1 = unpack2(a1);
        float r0 = u0.x + u0.y, r1 = u1.x + u1.y;
        r0 += __shfl_xor_sync(FULL, r0, 16);    // merge i-halves
        r1 += __shfl_xor_sync(FULL, r1, 16);
        if (ih == 0) {
            sS[nl][e0]     = r0;
            sS[nl][e0 + 1] = r1;
        }
    }
    __syncthreads();

    // Cooperative coalesced store of the [nodes][64] tile.
    const int nmax = min(PB_NODES, N_NODES - n0);
    for (int idx = threadIdx.x; idx < nmax * EDIM; idx += 256) {
        int r = idx >> 6, e = idx & 63;
        dst[(n0 + r) * EDIM + e] = sS[r][e];
    }
}

// ---------------------------------------------------------------------------
// Kernel 2: gather + attention + aggregate. R5 layout (empirical optimum):
// warp per node, half = lane>>4 handles neighbor 2t+half, lane owns float4
// at foff=(lane&15)*4 (each LDG.128 covers the 2 cache lines of a neighbor
// row exactly — wavefront-optimal). Max-free softmax in exp2 domain.
// NEW: leaky_relu folded into the dot via |x| (lrelu(x)=0.505x+0.495|x|),
// packed f32x2 adds for q+k and packed fma for the aggregation.
// ---------------------------------------------------------------------------
__global__ __launch_bounds__(256) void gat_kernel(
    const int*   __restrict__ adj,    // [N_NODES][DEG]
    const float* __restrict__ aw,     // [EDIM]
    float*       __restrict__ out)    // [EDIM][N_NODES]
{
    const unsigned FULL = 0xffffffffu;
    const float LOG2E = 1.4426950408889634f;
    const int warp = threadIdx.x >> 5;
    const int lane = threadIdx.x & 31;
    const int half = lane >> 4;
    const int foff = (lane & 15) * 4;
    const int n = blockIdx.x * 8 + warp;          // grid exact: 6250*8 = 50000

    __shared__ float sOut[EDIM][9];               // pitch 9 to spread banks

    int j = adj[n * DEG + lane];
    ulonglong2 qp = *reinterpret_cast<const ulonglong2*>(&g_Qf[n * EDIM + foff]);
    float4 w4 = *reinterpret_cast<const float4*>(&aw[foff]);
    // lrelu(x) = 0.505x + 0.495|x|  (slope 0.01); fold log2(e) for exp2 domain
    const float c1 = 0.505f * LOG2E, c2 = 0.495f * LOG2E;
    float w1x = w4.x * c1, w1y = w4.y * c1, w1z = w4.z * c1, w1w = w4.w * c1;
    float w2x = w4.x * c2, w2y = w4.y * c2, w2z = w4.z * c2, w2w = w4.w * c2;

    float s = 0.f;
    ull accA = 0ull, accB = 0ull;

#pragma unroll
    for (int t = 0; t < DEG / 2; t++) {
        int jk = __shfl_sync(FULL, j, (t << 1) | half);
        ulonglong2 kp = make_ulonglong2(0ull, 0ull);
        if (jk >= 0)   // uniform within half-warp
            kp = *reinterpret_cast<const ulonglong2*>(&g_Kf[jk * EDIM + foff]);

        // x = q + k (packed), dot with split weights (|x| folds into FFMA)
        float2 xa = unpack2(add2(qp.x, kp.x));
        float2 xb = unpack2(add2(qp.y, kp.y));
        float p1, p2;
        p1 = w1x * xa.x;             p2 = w2x * fabsf(xa.x);
        p1 = fmaf(w1y, xa.y, p1);    p2 = fmaf(w2y, fabsf(xa.y), p2);
        p1 = fmaf(w1z, xb.x, p1);    p2 = fmaf(w2z, fabsf(xb.x), p2);
        p1 = fmaf(w1w, xb.y, p1);    p2 = fmaf(w2w, fabsf(xb.y), p2);
        float p = p1 + p2;

        // reduce over 16 out-features of this head (4 lanes x 4 feats)
        p += __shfl_xor_sync(FULL, p, 1);
        p += __shfl_xor_sync(FULL, p, 2);

        // max-free softmax term; padded edge -> weight 0
        float e = (jk >= 0) ? ex2f(p) : 0.f;
        s += e;
        ull e2 = pack2(e, e);
        fma2(accA, e2, kp.x);
        fma2(accB, e2, kp.y);
    }

    // merge the two halves (even/odd neighbors); same features at lane^16
    float2 A = unpack2(accA), B = unpack2(accB);
    s   += __shfl_xor_sync(FULL, s, 16);
    A.x += __shfl_xor_sync(FULL, A.x, 16);
    A.y += __shfl_xor_sync(FULL, A.y, 16);
    B.x += __shfl_xor_sync(FULL, B.x, 16);
    B.y += __shfl_xor_sync(FULL, B.y, 16);

    // all-pad rows: s == 0, acc == 0 -> output exactly 0 (matches reference)
    float inv = __frcp_rn(fmaxf(s, 1e-30f));
    if (half == 0) {
        sOut[foff + 0][warp] = A.x * inv;
        sOut[foff + 1][warp] = A.y * inv;
        sOut[foff + 2][warp] = B.x * inv;
        sOut[foff + 3][warp] = B.y * inv;
    }
    __syncthreads();

    // Coalesced store: 512 elements, 8 consecutive n per feature row.
    const int n0 = blockIdx.x * 8;
#pragma unroll
    for (int idx = threadIdx.x; idx < EDIM * 8; idx += 256) {
        int e  = idx >> 3;
        int nn = idx & 7;
        out[e * N_NODES + n0 + nn] = sOut[e][nn];
    }
}

// ---------------------------------------------------------------------------
extern "C" void kernel_launch(void* const* d_in, const int* in_sizes, int n_in,
                              void* d_out, int out_size)
{
    const int*   adj = (const int*)  d_in[0];   // [50000*32] int32
    const float* Q   = (const float*)d_in[1];   // [64*50000]
    const float* qw  = (const float*)d_in[2];   // [4*16*64]
    const float* kw  = (const float*)d_in[3];   // [4*16*64]
    const float* aw  = (const float*)d_in[4];   // [4*16]
    float* out = (float*)d_out;                 // [4*16*50000]

    (void)in_sizes; (void)n_in; (void)out_size;

    dim3 pgrid((N_NODES + PB_NODES - 1) / PB_NODES, 2);   // 782 x 2
    proj_kernel<<<pgrid, 256>>>(Q, qw, kw);
    gat_kernel<<<N_NODES / 8, 256>>>(adj, aw, out);
}